// round 3
// baseline (speedup 1.0000x reference)
#include <cuda_runtime.h>
#include <cuda_bf16.h>
#include <math.h>

#define N_NODES 100000
#define N_EDGES 1600000
#define N_TOT   1700000   // edges + self loops
#define N_GRAPHS 256
#define BN_EPS 1e-5f

#define SCAN_BLOCKS 512
#define SCAN_CHUNK  ((N_NODES + SCAN_BLOCKS - 1) / SCAN_BLOCKS)   // 196

// ---------------- scratch (device globals; no runtime allocation) -------------
__device__ int   g_idx64;               // 1 if indices are int64, 0 if int32
__device__ int   g_deg[N_NODES];
__device__ float g_dinv[N_NODES];
__device__ int   g_off[N_NODES + 1];
__device__ int   g_blocksum[SCAN_BLOCKS];
__device__ int   g_cursor[N_NODES];
__device__ int   g_srcarr[N_TOT];
__device__ float g_normarr[N_TOT];
__device__ float g_hA[(size_t)N_NODES * 199];  // GEMM output (pre-aggregation)
__device__ float g_hB[(size_t)N_NODES * 199];  // aggregation output (= next layer input)
__device__ float g_stats[512];                 // [0..255]=sum, [256..511]=sumsq
__device__ float g_scale[256];
__device__ float g_shift[256];
__device__ int   g_gstart[N_GRAPHS + 1];

// dual-width index loader
__device__ __forceinline__ int idx_at(const void* p, long i, int is64) {
    if (is64) return (int)((const long long*)p)[i];
    return ((const int*)p)[i];
}

// ---------------- dtype detection ----------------
__global__ void __launch_bounds__(32) k_detect(const int* __restrict__ ei32) {
    if (threadIdx.x != 0) return;
    // int64 little-endian values < 2^31: all odd 32-bit words are 0.
    int any = 0;
    for (int k = 0; k < 64; k++) {
        if (ei32[2 * k + 1] != 0) { any = 1; break; }
    }
    g_idx64 = !any;
}

// ---------------- graph prep ----------------
__global__ void __launch_bounds__(256) k_deg_init() {
    int n = blockIdx.x * blockDim.x + threadIdx.x;
    if (n < N_NODES) g_deg[n] = 1;  // self loop
}

__global__ void __launch_bounds__(256) k_deg_edges(const void* __restrict__ ei) {
    int e = blockIdx.x * blockDim.x + threadIdx.x;
    if (e < N_EDGES) {
        int is64 = g_idx64;
        int d = idx_at(ei, (long)N_EDGES + e, is64);  // dst row
        if ((unsigned)d < N_NODES) atomicAdd(&g_deg[d], 1);
    }
}

__global__ void __launch_bounds__(256) k_dinv() {
    int n = blockIdx.x * blockDim.x + threadIdx.x;
    if (n < N_NODES) g_dinv[n] = rsqrtf((float)g_deg[n]);
}

// pass 1: per-block exclusive scan over a CHUNK*... span; writes block totals
__global__ void __launch_bounds__(256) k_scan1() {
    __shared__ int sh[256];
    int b = blockIdx.x;
    int t = threadIdx.x;
    const int PER_T = (SCAN_CHUNK + 255) / 256;  // ceil(196/256)=1
    int base = b * SCAN_CHUNK;
    int s = 0;
    int vals[PER_T];
    #pragma unroll
    for (int i = 0; i < PER_T; i++) {
        int idx = base + t * PER_T + i;
        int v = (idx < N_NODES && t * PER_T + i < SCAN_CHUNK) ? g_deg[idx] : 0;
        vals[i] = v;
        s += v;
    }
    sh[t] = s;
    __syncthreads();
    // block-level inclusive scan
    for (int o = 1; o < 256; o <<= 1) {
        int v = (t >= o) ? sh[t - o] : 0;
        __syncthreads();
        sh[t] += v;
        __syncthreads();
    }
    int pre = (t == 0) ? 0 : sh[t - 1];
    #pragma unroll
    for (int i = 0; i < PER_T; i++) {
        int idx = base + t * PER_T + i;
        if (idx < N_NODES && t * PER_T + i < SCAN_CHUNK) {
            g_off[idx] = pre;   // local exclusive offset; fixed up in pass 3
            pre += vals[i];
        }
    }
    if (t == 255) g_blocksum[b] = sh[255];
}

// pass 2: scan block sums (single block of 256 covering 512 sums, 2 each)
__global__ void __launch_bounds__(256) k_scan2() {
    __shared__ int sh[256];
    int t = threadIdx.x;
    int a0 = g_blocksum[2 * t];
    int a1 = g_blocksum[2 * t + 1];
    sh[t] = a0 + a1;
    __syncthreads();
    for (int o = 1; o < 256; o <<= 1) {
        int v = (t >= o) ? sh[t - o] : 0;
        __syncthreads();
        sh[t] += v;
        __syncthreads();
    }
    int pre = (t == 0) ? 0 : sh[t - 1];
    g_blocksum[2 * t] = pre;
    g_blocksum[2 * t + 1] = pre + a0;
    if (t == 255) g_off[N_NODES] = sh[255];
}

// pass 3: add block offsets
__global__ void __launch_bounds__(256) k_scan3() {
    int n = blockIdx.x * blockDim.x + threadIdx.x;
    if (n < N_NODES) g_off[n] += g_blocksum[n / SCAN_CHUNK];
}

__global__ void __launch_bounds__(256) k_selfloop() {
    int n = blockIdx.x * blockDim.x + threadIdx.x;
    if (n < N_NODES) {
        int o = g_off[n];
        g_srcarr[o] = n;
        float di = g_dinv[n];
        g_normarr[o] = di * di;
        g_cursor[n] = o + 1;
    }
}

__global__ void __launch_bounds__(256) k_fill(const void* __restrict__ ei) {
    int e = blockIdx.x * blockDim.x + threadIdx.x;
    if (e < N_EDGES) {
        int is64 = g_idx64;
        int s = idx_at(ei, e, is64);
        int d = idx_at(ei, (long)N_EDGES + e, is64);
        if ((unsigned)s < N_NODES && (unsigned)d < N_NODES) {
            int pos = atomicAdd(&g_cursor[d], 1);
            if ((unsigned)pos < N_TOT) {
                g_srcarr[pos] = s;
                g_normarr[pos] = g_dinv[s] * g_dinv[d];
            }
        }
    }
}

// ---------------- batchnorm stats ----------------
__global__ void __launch_bounds__(512) k_zero_stats() {
    int i = threadIdx.x;
    if (i < 512) g_stats[i] = 0.0f;
}

// grid (ceil(FI/32), 64), block (32, 8). Column-parallel: coalesced loads.
__global__ void __launch_bounds__(256) k_stats(const float* __restrict__ xp, int FI, int useParam) {
    const float* x = useParam ? xp : g_hB;
    int f = blockIdx.x * 32 + threadIdx.x;
    float s = 0.f, sq = 0.f;
    if (f < FI) {
        for (int n = blockIdx.y * blockDim.y + threadIdx.y; n < N_NODES;
             n += gridDim.y * blockDim.y) {
            float v = x[(size_t)n * FI + f];
            s += v;
            sq += v * v;
        }
    }
    __shared__ float shs[8][32];
    __shared__ float shq[8][32];
    shs[threadIdx.y][threadIdx.x] = s;
    shq[threadIdx.y][threadIdx.x] = sq;
    __syncthreads();
    if (threadIdx.y == 0 && f < FI) {
        float ts = 0.f, tq = 0.f;
        #pragma unroll
        for (int y = 0; y < 8; y++) { ts += shs[y][threadIdx.x]; tq += shq[y][threadIdx.x]; }
        atomicAdd(&g_stats[f], ts);
        atomicAdd(&g_stats[256 + f], tq);
    }
}

__global__ void __launch_bounds__(256) k_finalize(const float* __restrict__ gam,
                                                  const float* __restrict__ bet, int FI) {
    int k = threadIdx.x;
    if (k < FI) {
        float m = g_stats[k] * (1.0f / N_NODES);
        float v = g_stats[256 + k] * (1.0f / N_NODES) - m * m;
        float a = gam[k] * rsqrtf(v + BN_EPS);
        g_scale[k] = a;
        g_shift[k] = bet[k] - m * a;
    }
}

// ---------------- GEMM: out = BN(in) @ W  (register-tiled 4x4) ----------------
// grid (ceil(N/64), ceil(FO/64)), block 256
template <int FI, int FO, bool IN_PARAM>
__global__ void __launch_bounds__(256) k_gemm(const float* __restrict__ inp,
                                              const float* __restrict__ W) {
    const int KC = 32;
    __shared__ float xs[64][KC + 1];
    __shared__ float ws[KC][64];
    const float* in = IN_PARAM ? inp : g_hB;
    float* out = g_hA;

    int tid = threadIdx.x;
    int tx = tid & 15, ty = tid >> 4;
    int n0 = blockIdx.x * 64, j0 = blockIdx.y * 64;

    float acc[4][4];
    #pragma unroll
    for (int r = 0; r < 4; r++)
        #pragma unroll
        for (int c = 0; c < 4; c++) acc[r][c] = 0.f;

    for (int kc = 0; kc < FI; kc += KC) {
        // stage x tile (BN applied)
        for (int i = tid; i < 64 * KC; i += 256) {
            int nn = i / KC, kk = i % KC;
            int k = kc + kk, n = n0 + nn;
            float v = 0.f;
            if (k < FI && n < N_NODES) v = g_scale[k] * in[(size_t)n * FI + k] + g_shift[k];
            xs[nn][kk] = v;
        }
        // stage W tile
        for (int i = tid; i < KC * 64; i += 256) {
            int kk = i / 64, c = i % 64;
            int k = kc + kk, j = j0 + c;
            float v = 0.f;
            if (k < FI && j < FO) v = W[k * FO + j];
            ws[kk][c] = v;
        }
        __syncthreads();
        int kmax = (FI - kc < KC) ? (FI - kc) : KC;
        for (int kk = 0; kk < kmax; kk++) {
            float w0 = ws[kk][tx * 4 + 0];
            float w1 = ws[kk][tx * 4 + 1];
            float w2 = ws[kk][tx * 4 + 2];
            float w3 = ws[kk][tx * 4 + 3];
            float xv[4];
            #pragma unroll
            for (int r = 0; r < 4; r++) xv[r] = xs[ty * 4 + r][kk];
            #pragma unroll
            for (int r = 0; r < 4; r++) {
                acc[r][0] += xv[r] * w0;
                acc[r][1] += xv[r] * w1;
                acc[r][2] += xv[r] * w2;
                acc[r][3] += xv[r] * w3;
            }
        }
        __syncthreads();
    }
    #pragma unroll
    for (int r = 0; r < 4; r++) {
        int n = n0 + ty * 4 + r;
        if (n >= N_NODES) continue;
        #pragma unroll
        for (int c = 0; c < 4; c++) {
            int j = j0 + tx * 4 + c;
            if (j < FO) out[(size_t)n * FO + j] = acc[r][c];
        }
    }
}

// ---------------- aggregation (CSR gather, no atomics) + bias + relu ----------
// one warp per destination node
template <int FO, int NF>
__global__ void __launch_bounds__(256) k_gather(const float* __restrict__ bias) {
    int w = (blockIdx.x * blockDim.x + threadIdx.x) >> 5;
    int lane = threadIdx.x & 31;
    if (w >= N_NODES) return;
    int beg = g_off[w], end = g_off[w + 1];
    float acc[NF];
    #pragma unroll
    for (int f = 0; f < NF; f++) acc[f] = 0.f;

    for (int e = beg; e < end; e++) {
        int s = __ldg(&g_srcarr[e]);
        float wn = __ldg(&g_normarr[e]);
        const float* row = g_hA + (size_t)s * FO;
        #pragma unroll
        for (int f = 0; f < NF; f++) {
            int c = lane + 32 * f;
            if ((FO % 32 == 0) || c < FO) acc[f] += wn * __ldg(&row[c]);
        }
    }
    #pragma unroll
    for (int f = 0; f < NF; f++) {
        int c = lane + 32 * f;
        if (c < FO) {
            float v = acc[f] + __ldg(&bias[c]);
            g_hB[(size_t)w * FO + c] = v > 0.f ? v : 0.f;
        }
    }
}

// ---------------- pooling boundaries (batch is sorted) ----------------
__global__ void __launch_bounds__(256) k_gstart(const void* __restrict__ batch) {
    int g = blockIdx.x * blockDim.x + threadIdx.x;
    if (g > N_GRAPHS) return;
    if (g == N_GRAPHS) { g_gstart[g] = N_NODES; return; }
    int is64 = g_idx64;
    int lo = 0, hi = N_NODES;
    while (lo < hi) {
        int mid = (lo + hi) >> 1;
        if (idx_at(batch, mid, is64) < g) lo = mid + 1; else hi = mid;
    }
    g_gstart[g] = lo;
}

// ---------------- fused mean-pool + MLP head ----------------
// grid = 256 (one block per graph), block 256
__global__ void __launch_bounds__(256) k_poolmlp(const float* __restrict__ Wl1,
                                                 const float* __restrict__ bl1,
                                                 const float* __restrict__ Wl2,
                                                 const float* __restrict__ bl2,
                                                 float* __restrict__ out) {
    const int FO = 199;
    __shared__ float pooled[FO];
    __shared__ float t1[49];
    int g = blockIdx.x;
    int s = g_gstart[g], e = g_gstart[g + 1];
    int f = threadIdx.x;
    if (f < FO) {
        float acc = 0.f;
        for (int n = s; n < e; n++) acc += g_hB[(size_t)n * FO + f];
        int cnt = e - s;
        pooled[f] = acc / (float)(cnt > 0 ? cnt : 1);
    }
    __syncthreads();
    if (f < 49) {
        float a = bl1[f];
        for (int k = 0; k < FO; k++) a += pooled[k] * Wl1[k * 49 + f];
        t1[f] = a;
    }
    __syncthreads();
    if (f < 2) {
        float a = bl2[f];
        for (int k = 0; k < 49; k++) a += t1[k] * Wl2[k * 2 + f];
        out[g * 2 + f] = a;
    }
}

// ---------------- launch ----------------
extern "C" void kernel_launch(void* const* d_in, const int* in_sizes, int n_in,
                              void* d_out, int out_size) {
    const float* x     = (const float*)d_in[0];
    const void*  ei    = d_in[1];
    const void*  batch = d_in[2];
    const float* bn0g = (const float*)d_in[3];
    const float* bn0b = (const float*)d_in[4];
    const float* bn1g = (const float*)d_in[5];
    const float* bn1b = (const float*)d_in[6];
    const float* bn2g = (const float*)d_in[7];
    const float* bn2b = (const float*)d_in[8];
    const float* W1  = (const float*)d_in[9];
    const float* b1  = (const float*)d_in[10];
    const float* W2  = (const float*)d_in[11];
    const float* b2  = (const float*)d_in[12];
    const float* W3  = (const float*)d_in[13];
    const float* b3  = (const float*)d_in[14];
    const float* Wl1 = (const float*)d_in[15];
    const float* bl1 = (const float*)d_in[16];
    const float* Wl2 = (const float*)d_in[17];
    const float* bl2 = (const float*)d_in[18];
    float* out = (float*)d_out;

    const int NB_N = (N_NODES + 255) / 256;
    const int NB_E = (N_EDGES + 255) / 256;
    const int NB_W = (N_NODES * 32 + 255) / 256;  // warp-per-node grids

    // dtype detection + graph preprocessing
    k_detect<<<1, 32>>>((const int*)ei);
    k_deg_init<<<NB_N, 256>>>();
    k_deg_edges<<<NB_E, 256>>>(ei);
    k_dinv<<<NB_N, 256>>>();
    k_scan1<<<SCAN_BLOCKS, 256>>>();
    k_scan2<<<1, 256>>>();
    k_scan3<<<NB_N, 256>>>();
    k_selfloop<<<NB_N, 256>>>();
    k_fill<<<NB_E, 256>>>(ei);
    k_gstart<<<2, 256>>>(batch);

    dim3 sblk(32, 8);

    // ---- layer 1: bn0(x) -> gcn(W1,b1) -> relu
    k_zero_stats<<<1, 512>>>();
    k_stats<<<dim3(1, 64), sblk>>>(x, 7, 1);
    k_finalize<<<1, 256>>>(bn0g, bn0b, 7);
    k_gemm<7, 71, true><<<dim3((N_NODES + 63) / 64, 2), 256>>>(x, W1);
    k_gather<71, 3><<<NB_W, 256>>>(b1);

    // ---- layer 2: bn1(h) -> gcn(W2,b2) -> relu
    k_zero_stats<<<1, 512>>>();
    k_stats<<<dim3(3, 64), sblk>>>(nullptr, 71, 0);
    k_finalize<<<1, 256>>>(bn1g, bn1b, 71);
    k_gemm<71, 135, false><<<dim3((N_NODES + 63) / 64, 3), 256>>>(nullptr, W2);
    k_gather<135, 5><<<NB_W, 256>>>(b2);

    // ---- layer 3: bn2(h) -> gcn(W3,b3) -> relu
    k_zero_stats<<<1, 512>>>();
    k_stats<<<dim3(5, 64), sblk>>>(nullptr, 135, 0);
    k_finalize<<<1, 256>>>(bn2g, bn2b, 135);
    k_gemm<135, 199, false><<<dim3((N_NODES + 63) / 64, 4), 256>>>(nullptr, W3);
    k_gather<199, 7><<<NB_W, 256>>>(b3);

    // ---- pool + head
    k_poolmlp<<<N_GRAPHS, 256>>>(Wl1, bl1, Wl2, bl2, out);
}

// round 4
// speedup vs baseline: 1.2256x; 1.2256x over previous
#include <cuda_runtime.h>
#include <cuda_bf16.h>
#include <math.h>

#define N_NODES 100000
#define N_EDGES 1600000
#define N_TOT   1700000   // edges + self loops
#define N_GRAPHS 256
#define BN_EPS 1e-5f

#define SCAN_BLOCKS 512
#define SCAN_CHUNK  ((N_NODES + SCAN_BLOCKS - 1) / SCAN_BLOCKS)   // 196

// ---------------- scratch (device globals; no runtime allocation) -------------
__device__ int   g_idx64;               // 1 if indices are int64, 0 if int32
__device__ int   g_deg[N_NODES];
__device__ float g_dinv[N_NODES];
__device__ int   g_off[N_NODES + 1];
__device__ int   g_blocksum[SCAN_BLOCKS];
__device__ int   g_cursor[N_NODES];
__device__ int   g_srcarr[N_TOT];
__device__ float g_normarr[N_TOT];
__device__ float g_hA[(size_t)N_NODES * 199];  // aggregated (BN'd) input to GEMM
__device__ float g_hB[(size_t)N_NODES * 199];  // layer output (post bias+relu)
__device__ float g_stats[512];                 // [0..255]=sum, [256..511]=sumsq
__device__ float g_scale[256];
__device__ float g_shift[256];
__device__ int   g_gstart[N_GRAPHS + 1];

// dual-width index loader
__device__ __forceinline__ int idx_at(const void* p, long i, int is64) {
    if (is64) return (int)((const long long*)p)[i];
    return ((const int*)p)[i];
}

// ---------------- dtype detection ----------------
__global__ void __launch_bounds__(32) k_detect(const int* __restrict__ ei32) {
    if (threadIdx.x != 0) return;
    int any = 0;
    for (int k = 0; k < 64; k++) {
        if (ei32[2 * k + 1] != 0) { any = 1; break; }
    }
    g_idx64 = !any;
}

// ---------------- graph prep ----------------
__global__ void __launch_bounds__(256) k_deg_init() {
    int n = blockIdx.x * blockDim.x + threadIdx.x;
    if (n < N_NODES) g_deg[n] = 1;  // self loop
}

__global__ void __launch_bounds__(256) k_deg_edges(const void* __restrict__ ei) {
    int e = blockIdx.x * blockDim.x + threadIdx.x;
    if (e < N_EDGES) {
        int is64 = g_idx64;
        int d = idx_at(ei, (long)N_EDGES + e, is64);
        if ((unsigned)d < N_NODES) atomicAdd(&g_deg[d], 1);
    }
}

__global__ void __launch_bounds__(256) k_dinv() {
    int n = blockIdx.x * blockDim.x + threadIdx.x;
    if (n < N_NODES) g_dinv[n] = rsqrtf((float)g_deg[n]);
}

__global__ void __launch_bounds__(256) k_scan1() {
    __shared__ int sh[256];
    int b = blockIdx.x;
    int t = threadIdx.x;
    const int PER_T = (SCAN_CHUNK + 255) / 256;  // 1
    int base = b * SCAN_CHUNK;
    int s = 0;
    int vals[PER_T];
    #pragma unroll
    for (int i = 0; i < PER_T; i++) {
        int idx = base + t * PER_T + i;
        int v = (idx < N_NODES && t * PER_T + i < SCAN_CHUNK) ? g_deg[idx] : 0;
        vals[i] = v;
        s += v;
    }
    sh[t] = s;
    __syncthreads();
    for (int o = 1; o < 256; o <<= 1) {
        int v = (t >= o) ? sh[t - o] : 0;
        __syncthreads();
        sh[t] += v;
        __syncthreads();
    }
    int pre = (t == 0) ? 0 : sh[t - 1];
    #pragma unroll
    for (int i = 0; i < PER_T; i++) {
        int idx = base + t * PER_T + i;
        if (idx < N_NODES && t * PER_T + i < SCAN_CHUNK) {
            g_off[idx] = pre;
            pre += vals[i];
        }
    }
    if (t == 255) g_blocksum[b] = sh[255];
}

__global__ void __launch_bounds__(256) k_scan2() {
    __shared__ int sh[256];
    int t = threadIdx.x;
    int a0 = g_blocksum[2 * t];
    int a1 = g_blocksum[2 * t + 1];
    sh[t] = a0 + a1;
    __syncthreads();
    for (int o = 1; o < 256; o <<= 1) {
        int v = (t >= o) ? sh[t - o] : 0;
        __syncthreads();
        sh[t] += v;
        __syncthreads();
    }
    int pre = (t == 0) ? 0 : sh[t - 1];
    g_blocksum[2 * t] = pre;
    g_blocksum[2 * t + 1] = pre + a0;
    if (t == 255) g_off[N_NODES] = sh[255];
}

__global__ void __launch_bounds__(256) k_scan3() {
    int n = blockIdx.x * blockDim.x + threadIdx.x;
    if (n < N_NODES) g_off[n] += g_blocksum[n / SCAN_CHUNK];
}

__global__ void __launch_bounds__(256) k_selfloop() {
    int n = blockIdx.x * blockDim.x + threadIdx.x;
    if (n < N_NODES) {
        int o = g_off[n];
        g_srcarr[o] = n;
        float di = g_dinv[n];
        g_normarr[o] = di * di;
        g_cursor[n] = o + 1;
    }
}

__global__ void __launch_bounds__(256) k_fill(const void* __restrict__ ei) {
    int e = blockIdx.x * blockDim.x + threadIdx.x;
    if (e < N_EDGES) {
        int is64 = g_idx64;
        int s = idx_at(ei, e, is64);
        int d = idx_at(ei, (long)N_EDGES + e, is64);
        if ((unsigned)s < N_NODES && (unsigned)d < N_NODES) {
            int pos = atomicAdd(&g_cursor[d], 1);
            if ((unsigned)pos < N_TOT) {
                g_srcarr[pos] = s;
                g_normarr[pos] = g_dinv[s] * g_dinv[d];
            }
        }
    }
}

// ---------------- batchnorm stats ----------------
__global__ void __launch_bounds__(512) k_zero_stats() {
    int i = threadIdx.x;
    if (i < 512) g_stats[i] = 0.0f;
}

// grid (ceil(FI/32), 64), block (32, 8). Column-parallel: coalesced loads.
__global__ void __launch_bounds__(256) k_stats(const float* __restrict__ xp, int FI, int useParam) {
    const float* x = useParam ? xp : g_hB;
    int f = blockIdx.x * 32 + threadIdx.x;
    float s = 0.f, sq = 0.f;
    if (f < FI) {
        for (int n = blockIdx.y * blockDim.y + threadIdx.y; n < N_NODES;
             n += gridDim.y * blockDim.y) {
            float v = x[(size_t)n * FI + f];
            s += v;
            sq += v * v;
        }
    }
    __shared__ float shs[8][32];
    __shared__ float shq[8][32];
    shs[threadIdx.y][threadIdx.x] = s;
    shq[threadIdx.y][threadIdx.x] = sq;
    __syncthreads();
    if (threadIdx.y == 0 && f < FI) {
        float ts = 0.f, tq = 0.f;
        #pragma unroll
        for (int y = 0; y < 8; y++) { ts += shs[y][threadIdx.x]; tq += shq[y][threadIdx.x]; }
        atomicAdd(&g_stats[f], ts);
        atomicAdd(&g_stats[256 + f], tq);
    }
}

__global__ void __launch_bounds__(256) k_finalize(const float* __restrict__ gam,
                                                  const float* __restrict__ bet, int FI) {
    int k = threadIdx.x;
    if (k < FI) {
        float m = g_stats[k] * (1.0f / N_NODES);
        float v = g_stats[256 + k] * (1.0f / N_NODES) - m * m;
        float a = gam[k] * rsqrtf(v + BN_EPS);
        g_scale[k] = a;
        g_shift[k] = bet[k] - m * a;
    }
}

// ---------------- aggregation FIRST (CSR gather over FI dims) ----------------
// agg[n] = scale * (Σ_e w_e * in[src_e]) + shift * (Σ_e w_e)    (== Σ w_e * BN(in[src_e]))
// LPN lanes per node, NF features per lane
template <int FI, int LPN, int NF, bool IN_PARAM>
__global__ void __launch_bounds__(256) k_gather(const float* __restrict__ inp) {
    const float* in = IN_PARAM ? inp : g_hB;
    int gid = blockIdx.x * blockDim.x + threadIdx.x;
    int node = gid / LPN;
    int lane = gid % LPN;
    if (node >= N_NODES) return;
    int beg = g_off[node], end = g_off[node + 1];
    float acc[NF];
    #pragma unroll
    for (int f = 0; f < NF; f++) acc[f] = 0.f;
    float sumw = 0.f;

    for (int e = beg; e < end; e++) {
        int s = __ldg(&g_srcarr[e]);
        float wn = __ldg(&g_normarr[e]);
        sumw += wn;
        const float* row = in + (size_t)s * FI;
        #pragma unroll
        for (int f = 0; f < NF; f++) {
            int c = lane + LPN * f;
            if ((FI % LPN == 0) || c < FI) acc[f] += wn * __ldg(&row[c]);
        }
    }
    #pragma unroll
    for (int f = 0; f < NF; f++) {
        int c = lane + LPN * f;
        if ((FI % LPN == 0) || c < FI)
            g_hA[(size_t)node * FI + c] = g_scale[c] * acc[f] + g_shift[c] * sumw;
    }
}

// ---------------- GEMM: hB = relu(agg @ W + bias) (register-tiled 4x4) -------
// grid (ceil(N/64), ceil(FO/64)), block 256
template <int FI, int FO>
__global__ void __launch_bounds__(256) k_gemm(const float* __restrict__ W,
                                              const float* __restrict__ bias) {
    const int KC = 32;
    __shared__ float xs[64][KC + 1];
    __shared__ float ws[KC][64];
    const float* in = g_hA;
    float* out = g_hB;

    int tid = threadIdx.x;
    int tx = tid & 15, ty = tid >> 4;
    int n0 = blockIdx.x * 64, j0 = blockIdx.y * 64;

    float acc[4][4];
    #pragma unroll
    for (int r = 0; r < 4; r++)
        #pragma unroll
        for (int c = 0; c < 4; c++) acc[r][c] = 0.f;

    for (int kc = 0; kc < FI; kc += KC) {
        for (int i = tid; i < 64 * KC; i += 256) {
            int nn = i / KC, kk = i % KC;
            int k = kc + kk, n = n0 + nn;
            float v = 0.f;
            if (k < FI && n < N_NODES) v = in[(size_t)n * FI + k];
            xs[nn][kk] = v;
        }
        for (int i = tid; i < KC * 64; i += 256) {
            int kk = i / 64, c = i % 64;
            int k = kc + kk, j = j0 + c;
            float v = 0.f;
            if (k < FI && j < FO) v = W[k * FO + j];
            ws[kk][c] = v;
        }
        __syncthreads();
        int kmax = (FI - kc < KC) ? (FI - kc) : KC;
        for (int kk = 0; kk < kmax; kk++) {
            float4 wv = *(const float4*)&ws[kk][tx * 4];
            float xv[4];
            #pragma unroll
            for (int r = 0; r < 4; r++) xv[r] = xs[ty * 4 + r][kk];
            #pragma unroll
            for (int r = 0; r < 4; r++) {
                acc[r][0] += xv[r] * wv.x;
                acc[r][1] += xv[r] * wv.y;
                acc[r][2] += xv[r] * wv.z;
                acc[r][3] += xv[r] * wv.w;
            }
        }
        __syncthreads();
    }
    #pragma unroll
    for (int r = 0; r < 4; r++) {
        int n = n0 + ty * 4 + r;
        if (n >= N_NODES) continue;
        #pragma unroll
        for (int c = 0; c < 4; c++) {
            int j = j0 + tx * 4 + c;
            if (j < FO) {
                float v = acc[r][c] + __ldg(&bias[j]);
                out[(size_t)n * FO + j] = v > 0.f ? v : 0.f;
            }
        }
    }
}

// ---------------- pooling boundaries (batch is sorted) ----------------
__global__ void __launch_bounds__(256) k_gstart(const void* __restrict__ batch) {
    int g = blockIdx.x * blockDim.x + threadIdx.x;
    if (g > N_GRAPHS) return;
    if (g == N_GRAPHS) { g_gstart[g] = N_NODES; return; }
    int is64 = g_idx64;
    int lo = 0, hi = N_NODES;
    while (lo < hi) {
        int mid = (lo + hi) >> 1;
        if (idx_at(batch, mid, is64) < g) lo = mid + 1; else hi = mid;
    }
    g_gstart[g] = lo;
}

// ---------------- fused mean-pool + MLP head ----------------
__global__ void __launch_bounds__(256) k_poolmlp(const float* __restrict__ Wl1,
                                                 const float* __restrict__ bl1,
                                                 const float* __restrict__ Wl2,
                                                 const float* __restrict__ bl2,
                                                 float* __restrict__ out) {
    const int FO = 199;
    __shared__ float pooled[FO];
    __shared__ float t1[49];
    int g = blockIdx.x;
    int s = g_gstart[g], e = g_gstart[g + 1];
    int f = threadIdx.x;
    if (f < FO) {
        float acc = 0.f;
        for (int n = s; n < e; n++) acc += g_hB[(size_t)n * FO + f];
        int cnt = e - s;
        pooled[f] = acc / (float)(cnt > 0 ? cnt : 1);
    }
    __syncthreads();
    if (f < 49) {
        float a = bl1[f];
        for (int k = 0; k < FO; k++) a += pooled[k] * Wl1[k * 49 + f];
        t1[f] = a;
    }
    __syncthreads();
    if (f < 2) {
        float a = bl2[f];
        for (int k = 0; k < 49; k++) a += t1[k] * Wl2[k * 2 + f];
        out[g * 2 + f] = a;
    }
}

// ---------------- launch ----------------
extern "C" void kernel_launch(void* const* d_in, const int* in_sizes, int n_in,
                              void* d_out, int out_size) {
    const float* x     = (const float*)d_in[0];
    const void*  ei    = d_in[1];
    const void*  batch = d_in[2];
    const float* bn0g = (const float*)d_in[3];
    const float* bn0b = (const float*)d_in[4];
    const float* bn1g = (const float*)d_in[5];
    const float* bn1b = (const float*)d_in[6];
    const float* bn2g = (const float*)d_in[7];
    const float* bn2b = (const float*)d_in[8];
    const float* W1  = (const float*)d_in[9];
    const float* b1  = (const float*)d_in[10];
    const float* W2  = (const float*)d_in[11];
    const float* b2  = (const float*)d_in[12];
    const float* W3  = (const float*)d_in[13];
    const float* b3  = (const float*)d_in[14];
    const float* Wl1 = (const float*)d_in[15];
    const float* bl1 = (const float*)d_in[16];
    const float* Wl2 = (const float*)d_in[17];
    const float* bl2 = (const float*)d_in[18];
    float* out = (float*)d_out;

    const int NB_N = (N_NODES + 255) / 256;
    const int NB_E = (N_EDGES + 255) / 256;

    // dtype detection + graph preprocessing
    k_detect<<<1, 32>>>((const int*)ei);
    k_deg_init<<<NB_N, 256>>>();
    k_deg_edges<<<NB_E, 256>>>(ei);
    k_dinv<<<NB_N, 256>>>();
    k_scan1<<<SCAN_BLOCKS, 256>>>();
    k_scan2<<<1, 256>>>();
    k_scan3<<<NB_N, 256>>>();
    k_selfloop<<<NB_N, 256>>>();
    k_fill<<<NB_E, 256>>>(ei);
    k_gstart<<<2, 256>>>(batch);

    dim3 sblk(32, 8);
    const int NB_G8  = ((N_NODES * 8)  + 255) / 256;
    const int NB_G32 = ((N_NODES * 32) + 255) / 256;

    // ---- layer 1: stats(x) -> gather(BN(x)) -> gemm W1 (+b1, relu)
    k_zero_stats<<<1, 512>>>();
    k_stats<<<dim3(1, 64), sblk>>>(x, 7, 1);
    k_finalize<<<1, 256>>>(bn0g, bn0b, 7);
    k_gather<7, 8, 1, true><<<NB_G8, 256>>>(x);
    k_gemm<7, 71><<<dim3((N_NODES + 63) / 64, 2), 256>>>(W1, b1);

    // ---- layer 2
    k_zero_stats<<<1, 512>>>();
    k_stats<<<dim3(3, 64), sblk>>>(nullptr, 71, 0);
    k_finalize<<<1, 256>>>(bn1g, bn1b, 71);
    k_gather<71, 32, 3, false><<<NB_G32, 256>>>(nullptr);
    k_gemm<71, 135><<<dim3((N_NODES + 63) / 64, 3), 256>>>(W2, b2);

    // ---- layer 3
    k_zero_stats<<<1, 512>>>();
    k_stats<<<dim3(5, 64), sblk>>>(nullptr, 135, 0);
    k_finalize<<<1, 256>>>(bn2g, bn2b, 135);
    k_gather<135, 32, 5, false><<<NB_G32, 256>>>(nullptr);
    k_gemm<135, 199><<<dim3((N_NODES + 63) / 64, 4), 256>>>(W3, b3);

    // ---- pool + head
    k_poolmlp<<<N_GRAPHS, 256>>>(Wl1, bl1, Wl2, bl2, out);
}